// round 7
// baseline (speedup 1.0000x reference)
#include <cuda_runtime.h>
#include <cuda_bf16.h>
#include <math.h>
#include <stdint.h>

// Problem constants
#define Bc  2
#define Tc  2048
#define Dc  1024
#define Hc  16
#define HDc 64
#define Mc  (Bc * Tc)          // 4096
#define DD  (Dc * Dc)
#define ATTN_SCALE 0.125f

// Scratch (bf16 hi/lo everywhere)
static __device__ __align__(16) __nv_bfloat16 g_xhi[Mc * Dc], g_xlo[Mc * Dc];
static __device__ __align__(16) __nv_bfloat16 g_whi[4][DD], g_wlo[4][DD];
static __device__ __align__(16) __nv_bfloat16 g_qh[Mc * Dc], g_ql[Mc * Dc];
static __device__ __align__(16) __nv_bfloat16 g_kh[Mc * Dc], g_kl[Mc * Dc];
static __device__ __align__(16) __nv_bfloat16 g_vh[Mc * Dc], g_vl[Mc * Dc];
static __device__ __align__(16) __nv_bfloat16 g_yhi[Mc * Dc], g_ylo[Mc * Dc];

// ---------------------------------------------------------------------------
// PTX helpers — base-target-safe (mma.sync / ldmatrix / cp.async)
// ---------------------------------------------------------------------------
__device__ __forceinline__ uint32_t smem_u32(const void* p) {
    uint32_t a;
    asm("{ .reg .u64 t; cvta.to.shared.u64 t, %1; cvt.u32.u64 %0, t; }" : "=r"(a) : "l"(p));
    return a;
}
__device__ __forceinline__ void ldm_x4(uint32_t& r0, uint32_t& r1, uint32_t& r2,
                                       uint32_t& r3, uint32_t addr) {
    asm volatile("ldmatrix.sync.aligned.m8n8.x4.shared.b16 {%0,%1,%2,%3}, [%4];"
                 : "=r"(r0), "=r"(r1), "=r"(r2), "=r"(r3) : "r"(addr));
}
__device__ __forceinline__ void ldm_x4t(uint32_t& r0, uint32_t& r1, uint32_t& r2,
                                        uint32_t& r3, uint32_t addr) {
    asm volatile("ldmatrix.sync.aligned.m8n8.x4.trans.shared.b16 {%0,%1,%2,%3}, [%4];"
                 : "=r"(r0), "=r"(r1), "=r"(r2), "=r"(r3) : "r"(addr));
}
__device__ __forceinline__ void mma16816(float* d, const uint32_t* a, const uint32_t* b) {
    asm volatile("mma.sync.aligned.m16n8k16.row.col.f32.bf16.bf16.f32 "
                 "{%0,%1,%2,%3}, {%4,%5,%6,%7}, {%8,%9}, {%0,%1,%2,%3};"
                 : "+f"(d[0]), "+f"(d[1]), "+f"(d[2]), "+f"(d[3])
                 : "r"(a[0]), "r"(a[1]), "r"(a[2]), "r"(a[3]), "r"(b[0]), "r"(b[1]));
}
__device__ __forceinline__ void cp16(uint32_t dst, const void* src) {
    asm volatile("cp.async.cg.shared.global [%0], [%1], 16;" :: "r"(dst), "l"(src));
}
__device__ __forceinline__ void cp_commit() {
    asm volatile("cp.async.commit_group;" ::: "memory");
}
template <int N>
__device__ __forceinline__ void cp_wait() {
    asm volatile("cp.async.wait_group %0;" :: "n"(N) : "memory");
}
__device__ __forceinline__ uint32_t pack_hi2(float a, float b) {
    __nv_bfloat162 v = __floats2bfloat162_rn(a, b);
    return *(uint32_t*)&v;
}

// ---------------------------------------------------------------------------
// Fused fp32 -> bf16 hi/lo split: x + all 4 weights in one launch.
// ---------------------------------------------------------------------------
#define NX4 (Mc * Dc / 4)
#define NW4 (DD / 4)

__global__ void __launch_bounds__(256)
split_all(const float* __restrict__ x,
          const float* __restrict__ w0, const float* __restrict__ w1,
          const float* __restrict__ w2, const float* __restrict__ w3,
          __nv_bfloat16* __restrict__ xhi, __nv_bfloat16* __restrict__ xlo,
          __nv_bfloat16* __restrict__ whi, __nv_bfloat16* __restrict__ wlo)
{
    const size_t c = (size_t)blockIdx.x * 256 + threadIdx.x;
    const float* src;
    __nv_bfloat16 *ho, *lo_;
    if (c < NX4) {
        src = x + c * 4;
        ho = xhi + c * 4; lo_ = xlo + c * 4;
    } else {
        const size_t r = c - NX4;
        const int w = (int)(r >> 18);
        const size_t l = (r & (NW4 - 1)) * 4;
        const float* ws = (w == 0) ? w0 : (w == 1) ? w1 : (w == 2) ? w2 : w3;
        src = ws + l;
        ho = whi + (size_t)w * DD + l; lo_ = wlo + (size_t)w * DD + l;
    }
    const float4 v = *(const float4*)src;
    const __nv_bfloat16 h0 = __float2bfloat16(v.x);
    const __nv_bfloat16 h1 = __float2bfloat16(v.y);
    const __nv_bfloat16 h2 = __float2bfloat16(v.z);
    const __nv_bfloat16 h3 = __float2bfloat16(v.w);
    __nv_bfloat162 ha, hb, la, lb;
    ha.x = h0; ha.y = h1; hb.x = h2; hb.y = h3;
    la.x = __float2bfloat16(v.x - __bfloat162float(h0));
    la.y = __float2bfloat16(v.y - __bfloat162float(h1));
    lb.x = __float2bfloat16(v.z - __bfloat162float(h2));
    lb.y = __float2bfloat16(v.w - __bfloat162float(h3));
    ((__nv_bfloat162*)ho)[0] = ha; ((__nv_bfloat162*)ho)[1] = hb;
    ((__nv_bfloat162*)lo_)[0] = la; ((__nv_bfloat162*)lo_)[1] = lb;
}

// ---------------------------------------------------------------------------
// Packed-row GEMM: acc[m,n] = sum_k A[m,k]*W[n,k], bf16 hi/lo 3-term.
// K-block 32: each 128-B smem row = [hi 32elem | lo 32elem], 8-chunk XOR swizzle.
// Stage = A 16 KB + W 16 KB = 32 KB; 3 stages (96 KB); 2 CTAs/SM.
// MODE 0: fp32 out C[m*Dc+n].  MODE 1: qkv flat N=3072 -> head-layout bf16 hi/lo.
// ---------------------------------------------------------------------------
#define PK_STAGE 32768
#define PK_SMEM  (3 * PK_STAGE)
#define NKB 32

template <int MODE>
__global__ void __launch_bounds__(256, 2)
gemm_pk(const __nv_bfloat16* __restrict__ Ahi, const __nv_bfloat16* __restrict__ Alo,
        const __nv_bfloat16* __restrict__ Wh, const __nv_bfloat16* __restrict__ Wl,
        const float* __restrict__ b0, const float* __restrict__ b1,
        const float* __restrict__ b2, float* __restrict__ C,
        __nv_bfloat16* __restrict__ qh, __nv_bfloat16* __restrict__ ql,
        __nv_bfloat16* __restrict__ kh, __nv_bfloat16* __restrict__ kl,
        __nv_bfloat16* __restrict__ vh, __nv_bfloat16* __restrict__ vl)
{
    extern __shared__ char smem[];
    const uint32_t sb = smem_u32(smem);
    const int tid = threadIdx.x;
    const int lane = tid & 31;
    const int wid = tid >> 5;
    const int m0 = blockIdx.y * 128;
    const int n0 = blockIdx.x * 128;        // 0..3071 (MODE1) or 0..1023 (MODE0)
    const int wm = (wid & 1) * 64;
    const int wn = (wid >> 1) * 32;

    auto issue = [&](int kb, int buf) {
        const uint32_t so = sb + buf * PK_STAGE;
        // A: 128 rows x 8 chunks (c<4 hi, c>=4 lo); W: same at +16384
#pragma unroll
        for (int it = 0; it < 8; it++) {
            const int idx = it * 256 + tid;      // 0..2047
            const int tile = idx >> 10;          // 0=A, 1=W
            const int r = (idx >> 3) & 127;
            const int ch = idx & 7;
            const uint32_t dst = so + tile * 16384 + r * 128 +
                                 ((ch * 16) ^ ((r & 7) << 4));
            const int kk = kb * 32 + (ch & 3) * 8;
            const __nv_bfloat16* src;
            if (tile == 0) src = ((ch < 4) ? Ahi : Alo) + (size_t)(m0 + r) * Dc + kk;
            else           src = ((ch < 4) ? Wh  : Wl ) + (size_t)(n0 + r) * Dc + kk;
            cp16(dst, src);
        }
        cp_commit();
    };

    const int g = lane >> 3;
    const int lr = lane & 7;
    int aRow[4];
    uint32_t aSw[4];
#pragma unroll
    for (int mf = 0; mf < 4; mf++) {
        aRow[mf] = wm + mf * 16 + ((g & 1) ? 8 : 0) + lr;
        aSw[mf] = (uint32_t)((aRow[mf] & 7) << 4);
    }
    const uint32_t aKext = (g >= 2) ? 16u : 0u;
    int bRow[2];
    uint32_t bSw[2];
#pragma unroll
    for (int p = 0; p < 2; p++) {
        bRow[p] = wn + p * 16 + ((g >= 2) ? 8 : 0) + lr;
        bSw[p] = (uint32_t)((bRow[p] & 7) << 4);
    }
    const uint32_t bKext = (g & 1) ? 16u : 0u;

    float acc[4][4][4];
#pragma unroll
    for (int mf = 0; mf < 4; mf++)
#pragma unroll
        for (int nf = 0; nf < 4; nf++)
#pragma unroll
            for (int q = 0; q < 4; q++) acc[mf][nf][q] = 0.0f;

    issue(0, 0);
    issue(1, 1);

    for (int kb = 0; kb < NKB; kb++) {
        if (kb + 2 < NKB) { issue(kb + 2, (kb + 2) % 3); cp_wait<2>(); }
        else if (kb + 1 < NKB) cp_wait<1>();
        else cp_wait<0>();
        __syncthreads();

        const uint32_t bA = sb + (kb % 3) * PK_STAGE;
        const uint32_t bW = bA + 16384;

#pragma unroll
        for (int ks = 0; ks < 2; ks++) {
            uint32_t ah[4][4], al[4][4], bh[4][2], bl[4][2];
#pragma unroll
            for (int mf = 0; mf < 4; mf++) {
                const uint32_t roff = (uint32_t)(aRow[mf] * 128);
                ldm_x4(ah[mf][0], ah[mf][1], ah[mf][2], ah[mf][3],
                       bA + roff + (((uint32_t)(ks * 32) + aKext) ^ aSw[mf]));
                ldm_x4(al[mf][0], al[mf][1], al[mf][2], al[mf][3],
                       bA + roff + ((64u + (uint32_t)(ks * 32) + aKext) ^ aSw[mf]));
            }
#pragma unroll
            for (int p = 0; p < 2; p++) {
                const uint32_t roff = (uint32_t)(bRow[p] * 128);
                ldm_x4(bh[2 * p][0], bh[2 * p][1], bh[2 * p + 1][0], bh[2 * p + 1][1],
                       bW + roff + (((uint32_t)(ks * 32) + bKext) ^ bSw[p]));
                ldm_x4(bl[2 * p][0], bl[2 * p][1], bl[2 * p + 1][0], bl[2 * p + 1][1],
                       bW + roff + ((64u + (uint32_t)(ks * 32) + bKext) ^ bSw[p]));
            }
#pragma unroll
            for (int mf = 0; mf < 4; mf++)
#pragma unroll
                for (int nf = 0; nf < 4; nf++) {
                    mma16816(acc[mf][nf], ah[mf], bh[nf]);
                    mma16816(acc[mf][nf], ah[mf], bl[nf]);
                    mma16816(acc[mf][nf], al[mf], bh[nf]);
                }
        }
        __syncthreads();
    }

    const int tr = lane >> 2;
    const int tc2 = (lane & 3) * 2;

    if (MODE == 0) {
#pragma unroll
        for (int mf = 0; mf < 4; mf++)
#pragma unroll
            for (int nf = 0; nf < 4; nf++) {
                const int n = n0 + wn + nf * 8 + tc2;
                const float bb0 = b0[n], bb1 = b0[n + 1];
                const int mA = m0 + wm + mf * 16 + tr;
                const int mB = mA + 8;
                float2 vA, vB;
                vA.x = acc[mf][nf][0] + bb0; vA.y = acc[mf][nf][1] + bb1;
                vB.x = acc[mf][nf][2] + bb0; vB.y = acc[mf][nf][3] + bb1;
                *(float2*)(C + (size_t)mA * Dc + n) = vA;
                *(float2*)(C + (size_t)mB * Dc + n) = vB;
            }
    } else {
        const int w = n0 >> 10;              // which weight (whole CTA)
        const int nl0 = n0 & 1023;
        const float scl = (w == 0) ? ATTN_SCALE : 1.0f;
        const float* bias = (w == 0) ? b0 : (w == 1) ? b1 : b2;
        __nv_bfloat16* oh = (w == 0) ? qh : (w == 1) ? kh : vh;
        __nv_bfloat16* ol = (w == 0) ? ql : (w == 1) ? kl : vl;
#pragma unroll
        for (int mf = 0; mf < 4; mf++)
#pragma unroll
            for (int nf = 0; nf < 4; nf++) {
                const int n = nl0 + wn + nf * 8 + tc2;
                const float bb0 = bias[n], bb1 = bias[n + 1];
                const int mA = m0 + wm + mf * 16 + tr;
                const int mB = mA + 8;
                const float vA0 = (acc[mf][nf][0] + bb0) * scl;
                const float vA1 = (acc[mf][nf][1] + bb1) * scl;
                const float vB0 = (acc[mf][nf][2] + bb0) * scl;
                const float vB1 = (acc[mf][nf][3] + bb1) * scl;
                const int hh = n >> 6, hd = n & 63;
                const int bA = mA >> 11, tA = mA & 2047;
                const int bB = mB >> 11, tB = mB & 2047;
                const size_t oA = ((size_t)(bA * Hc + hh) * Tc + tA) * HDc + hd;
                const size_t oB = ((size_t)(bB * Hc + hh) * Tc + tB) * HDc + hd;
                __nv_bfloat162 hA = __floats2bfloat162_rn(vA0, vA1);
                __nv_bfloat162 hB = __floats2bfloat162_rn(vB0, vB1);
                __nv_bfloat162 lA, lB;
                lA.x = __float2bfloat16(vA0 - __bfloat162float(hA.x));
                lA.y = __float2bfloat16(vA1 - __bfloat162float(hA.y));
                lB.x = __float2bfloat16(vB0 - __bfloat162float(hB.x));
                lB.y = __float2bfloat16(vB1 - __bfloat162float(hB.y));
                *(__nv_bfloat162*)(oh + oA) = hA;
                *(__nv_bfloat162*)(oh + oB) = hB;
                *(__nv_bfloat162*)(ol + oA) = lA;
                *(__nv_bfloat162*)(ol + oB) = lB;
            }
    }
}

// ---------------------------------------------------------------------------
// Tensor-core causal flash attention. BQ=128 (16 q-rows/warp), BKV=64.
// 2-stage cp.async KV pipeline; smem Q 32 KB + 2 x 32 KB = 96 KB; 2 CTAs/SM.
// ---------------------------------------------------------------------------
#define FL_SMEM (32768 + 2 * 32768)

__global__ void __launch_bounds__(256, 2)
flash_mma(const __nv_bfloat16* __restrict__ Qh_, const __nv_bfloat16* __restrict__ Ql_,
          const __nv_bfloat16* __restrict__ Kh_, const __nv_bfloat16* __restrict__ Kl_,
          const __nv_bfloat16* __restrict__ Vh_, const __nv_bfloat16* __restrict__ Vl_,
          __nv_bfloat16* __restrict__ Yhi, __nv_bfloat16* __restrict__ Ylo)
{
    extern __shared__ char smem[];
    const uint32_t sb = smem_u32(smem);
    const int tid = threadIdx.x;
    const int lane = tid & 31;
    const int w = tid >> 5;
    const int qi = (int)(gridDim.x - 1) - (int)blockIdx.x;   // heavy tiles first
    const int q0 = qi * 128;
    const int h = blockIdx.y, b = blockIdx.z;
    const size_t base = (size_t)(b * Hc + h) * Tc * HDc;
    const __nv_bfloat16* Qh = Qh_ + base;
    const __nv_bfloat16* Ql = Ql_ + base;
    const __nv_bfloat16* Kh = Kh_ + base;
    const __nv_bfloat16* Kl = Kl_ + base;
    const __nv_bfloat16* Vh = Vh_ + base;
    const __nv_bfloat16* Vl = Vl_ + base;

    // Q tiles (Qh at 0, Ql at 16384)
#pragma unroll
    for (int it = 0; it < 4; it++) {
        const int idx = it * 256 + tid;
        const int r = idx >> 3;
        const int ch = idx & 7;
        const uint32_t off = r * 128 + ((ch * 16) ^ ((r & 7) << 4));
        const size_t gi = (size_t)(q0 + r) * HDc + ch * 8;
        cp16(sb + off, Qh + gi);
        cp16(sb + 16384 + off, Ql + gi);
    }
    cp_commit();

    auto issueKV = [&](int t) {
        const int k0 = t * 64;
        const uint32_t so = sb + 32768 + (t & 1) * 32768;
#pragma unroll
        for (int it = 0; it < 2; it++) {
            const int idx = it * 256 + tid;
            const int r = idx >> 3;
            const int ch = idx & 7;
            const uint32_t off = r * 128 + ((ch * 16) ^ ((r & 7) << 4));
            const size_t gi = (size_t)(k0 + r) * HDc + ch * 8;
            cp16(so + off,         Kh + gi);
            cp16(so + 8192 + off,  Kl + gi);
            cp16(so + 16384 + off, Vh + gi);
            cp16(so + 24576 + off, Vl + gi);
        }
        cp_commit();
    };

    const int g = lane >> 3;
    const int lr = lane & 7;
    const int aRow = w * 16 + ((g & 1) ? 8 : 0) + lr;
    const uint32_t aSw = (uint32_t)((aRow & 7) << 4);
    const uint32_t aKext = (g >= 2) ? 16u : 0u;
    const int bRowBase = ((g >= 2) ? 8 : 0) + lr;
    const uint32_t bKext = (g & 1) ? 16u : 0u;
    const int vRow = lane & 15;
    const uint32_t vDext = (lane & 16) ? 16u : 0u;

    const int tr = lane >> 2;
    const int tc2 = (lane & 3) * 2;
    const int rowg0 = q0 + w * 16 + tr;
    const int rowg1 = rowg0 + 8;

    float mL[2] = { -INFINITY, -INFINITY };
    float lL[2] = { 0.0f, 0.0f };
    float o[8][4];
#pragma unroll
    for (int j = 0; j < 8; j++)
#pragma unroll
        for (int q = 0; q < 4; q++) o[j][q] = 0.0f;

    const int nt = q0 / 64 + 2;
    issueKV(0);

    for (int t = 0; t < nt; t++) {
        const int k0 = t * 64;
        if (t + 1 < nt) { issueKV(t + 1); cp_wait<1>(); }
        else            { cp_wait<0>(); }
        __syncthreads();

        if (k0 <= q0 + w * 16 + 15) {
            const uint32_t so = sb + 32768 + (t & 1) * 32768;
            float s[8][4];
#pragma unroll
            for (int j = 0; j < 8; j++)
#pragma unroll
                for (int q = 0; q < 4; q++) s[j][q] = 0.0f;

            // S = Q K^T (3-term)
#pragma unroll
            for (int ks = 0; ks < 4; ks++) {
                const uint32_t ka = (uint32_t)(ks * 32) + aKext;
                uint32_t qh4[4], ql4[4];
                const uint32_t qoff = (uint32_t)(aRow * 128) + (ka ^ aSw);
                ldm_x4(qh4[0], qh4[1], qh4[2], qh4[3], sb + qoff);
                ldm_x4(ql4[0], ql4[1], ql4[2], ql4[3], sb + 16384 + qoff);
#pragma unroll
                for (int p = 0; p < 4; p++) {
                    const int row = p * 16 + bRowBase;
                    const uint32_t off = (uint32_t)(row * 128) +
                        (((uint32_t)(ks * 32) + bKext) ^ ((uint32_t)((row & 7) << 4)));
                    uint32_t kh2[2][2], kl2[2][2];
                    ldm_x4(kh2[0][0], kh2[0][1], kh2[1][0], kh2[1][1], so + off);
                    ldm_x4(kl2[0][0], kl2[0][1], kl2[1][0], kl2[1][1], so + 8192 + off);
#pragma unroll
                    for (int u = 0; u < 2; u++) {
                        mma16816(s[2 * p + u], qh4, kh2[u]);
                        mma16816(s[2 * p + u], qh4, kl2[u]);
                        mma16816(s[2 * p + u], ql4, kh2[u]);
                    }
                }
            }

            // Causal mask
            if (k0 + 63 > q0 + w * 16) {
#pragma unroll
                for (int j = 0; j < 8; j++) {
                    const int c = k0 + j * 8 + tc2;
                    if (c > rowg0)     s[j][0] = -INFINITY;
                    if (c + 1 > rowg0) s[j][1] = -INFINITY;
                    if (c > rowg1)     s[j][2] = -INFINITY;
                    if (c + 1 > rowg1) s[j][3] = -INFINITY;
                }
            }

            // Online softmax
#pragma unroll
            for (int half = 0; half < 2; half++) {
                const int i0 = half * 2;
                float mx = -INFINITY;
#pragma unroll
                for (int j = 0; j < 8; j++)
                    mx = fmaxf(mx, fmaxf(s[j][i0], s[j][i0 + 1]));
                mx = fmaxf(mx, __shfl_xor_sync(0xffffffffu, mx, 1));
                mx = fmaxf(mx, __shfl_xor_sync(0xffffffffu, mx, 2));
                const float mn = fmaxf(mL[half], mx);
                const float alpha = __expf(mL[half] - mn);
                float rs = 0.0f;
#pragma unroll
                for (int j = 0; j < 8; j++) {
                    const float p0 = __expf(s[j][i0] - mn);
                    const float p1 = __expf(s[j][i0 + 1] - mn);
                    s[j][i0] = p0; s[j][i0 + 1] = p1;
                    rs += p0 + p1;
                }
                rs += __shfl_xor_sync(0xffffffffu, rs, 1);
                rs += __shfl_xor_sync(0xffffffffu, rs, 2);
                lL[half] = lL[half] * alpha + rs;
                mL[half] = mn;
#pragma unroll
                for (int j = 0; j < 8; j++) {
                    o[j][i0] *= alpha;
                    o[j][i0 + 1] *= alpha;
                }
            }

            // O += P V (3-term)
#pragma unroll
            for (int ks = 0; ks < 4; ks++) {
                const int j0 = 2 * ks, j1 = j0 + 1;
                uint32_t pha[4], pla[4];
                {
                    const float a0 = s[j0][0], a1 = s[j0][1];
                    const float a2 = s[j0][2], a3 = s[j0][3];
                    const float c0 = s[j1][0], c1 = s[j1][1];
                    const float c2 = s[j1][2], c3 = s[j1][3];
                    pha[0] = pack_hi2(a0, a1); pha[1] = pack_hi2(a2, a3);
                    pha[2] = pack_hi2(c0, c1); pha[3] = pack_hi2(c2, c3);
                    const __nv_bfloat162* hp0 = (const __nv_bfloat162*)&pha[0];
                    const __nv_bfloat162* hp1 = (const __nv_bfloat162*)&pha[1];
                    const __nv_bfloat162* hp2 = (const __nv_bfloat162*)&pha[2];
                    const __nv_bfloat162* hp3 = (const __nv_bfloat162*)&pha[3];
                    pla[0] = pack_hi2(a0 - __bfloat162float(hp0->x), a1 - __bfloat162float(hp0->y));
                    pla[1] = pack_hi2(a2 - __bfloat162float(hp1->x), a3 - __bfloat162float(hp1->y));
                    pla[2] = pack_hi2(c0 - __bfloat162float(hp2->x), c1 - __bfloat162float(hp2->y));
                    pla[3] = pack_hi2(c2 - __bfloat162float(hp3->x), c3 - __bfloat162float(hp3->y));
                }
                const int vr = ks * 16 + vRow;
                const uint32_t vsw = (uint32_t)((vr & 7) << 4);
#pragma unroll
                for (int pp = 0; pp < 4; pp++) {
                    const uint32_t dbyte = (uint32_t)(pp * 32) + vDext;
                    const uint32_t off = (uint32_t)(vr * 128) + (dbyte ^ vsw);
                    uint32_t vh2[2][2], vl2[2][2];
                    ldm_x4t(vh2[0][0], vh2[0][1], vh2[1][0], vh2[1][1], so + 16384 + off);
                    ldm_x4t(vl2[0][0], vl2[0][1], vl2[1][0], vl2[1][1], so + 24576 + off);
#pragma unroll
                    for (int u = 0; u < 2; u++) {
                        mma16816(o[2 * pp + u], pha, vh2[u]);
                        mma16816(o[2 * pp + u], pha, vl2[u]);
                        mma16816(o[2 * pp + u], pla, vh2[u]);
                    }
                }
            }
        }
        __syncthreads();
    }

    // Epilogue: y (B,T,D) bf16 hi/lo
    const float inv0 = 1.0f / lL[0];
    const float inv1 = 1.0f / lL[1];
#pragma unroll
    for (int j = 0; j < 8; j++) {
        const int col = h * HDc + j * 8 + tc2;
        const float y00 = o[j][0] * inv0, y01 = o[j][1] * inv0;
        const float y10 = o[j][2] * inv1, y11 = o[j][3] * inv1;
        const size_t o0 = ((size_t)(b * Tc + rowg0)) * Dc + col;
        const size_t o1 = ((size_t)(b * Tc + rowg1)) * Dc + col;
        __nv_bfloat162 h0 = __floats2bfloat162_rn(y00, y01);
        __nv_bfloat162 h1 = __floats2bfloat162_rn(y10, y11);
        __nv_bfloat162 l0, l1;
        l0.x = __float2bfloat16(y00 - __bfloat162float(h0.x));
        l0.y = __float2bfloat16(y01 - __bfloat162float(h0.y));
        l1.x = __float2bfloat16(y10 - __bfloat162float(h1.x));
        l1.y = __float2bfloat16(y11 - __bfloat162float(h1.y));
        *(__nv_bfloat162*)(Yhi + o0) = h0;
        *(__nv_bfloat162*)(Yhi + o1) = h1;
        *(__nv_bfloat162*)(Ylo + o0) = l0;
        *(__nv_bfloat162*)(Ylo + o1) = l1;
    }
}

// ---------------------------------------------------------------------------
// Launch
// ---------------------------------------------------------------------------
extern "C" void kernel_launch(void* const* d_in, const int* in_sizes, int n_in,
                              void* d_out, int out_size)
{
    const float* x  = (const float*)d_in[0];
    // d_in[1]: boolean causal mask (applied analytically)
    const float* Wq = (const float*)d_in[2];
    const float* bq = (const float*)d_in[3];
    const float* Wk = (const float*)d_in[4];
    const float* bk = (const float*)d_in[5];
    const float* Wv = (const float*)d_in[6];
    const float* bv = (const float*)d_in[7];
    const float* Wo = (const float*)d_in[8];
    const float* bo = (const float*)d_in[9];
    float* out = (float*)d_out;

    __nv_bfloat16 *xhi, *xlo, *whi, *wlo, *yhi, *ylo;
    __nv_bfloat16 *qh, *ql, *kh, *kl, *vh, *vl;
    cudaGetSymbolAddress((void**)&xhi, g_xhi);
    cudaGetSymbolAddress((void**)&xlo, g_xlo);
    cudaGetSymbolAddress((void**)&whi, g_whi);
    cudaGetSymbolAddress((void**)&wlo, g_wlo);
    cudaGetSymbolAddress((void**)&yhi, g_yhi);
    cudaGetSymbolAddress((void**)&ylo, g_ylo);
    cudaGetSymbolAddress((void**)&qh,  g_qh);
    cudaGetSymbolAddress((void**)&ql,  g_ql);
    cudaGetSymbolAddress((void**)&kh,  g_kh);
    cudaGetSymbolAddress((void**)&kl,  g_kl);
    cudaGetSymbolAddress((void**)&vh,  g_vh);
    cudaGetSymbolAddress((void**)&vl,  g_vl);

    cudaFuncSetAttribute(gemm_pk<0>, cudaFuncAttributeMaxDynamicSharedMemorySize, PK_SMEM);
    cudaFuncSetAttribute(gemm_pk<1>, cudaFuncAttributeMaxDynamicSharedMemorySize, PK_SMEM);
    cudaFuncSetAttribute(flash_mma, cudaFuncAttributeMaxDynamicSharedMemorySize, FL_SMEM);

    // Fused splits: x + Wq,Wk,Wv,Wo -> bf16 hi/lo
    split_all<<<(NX4 + 4 * NW4) / 256, 256>>>(x, Wq, Wk, Wv, Wo, xhi, xlo, whi, wlo);

    // QKV as one flat N=3072 GEMM against concatenated weights
    gemm_pk<1><<<dim3(3 * Dc / 128, Mc / 128), 256, PK_SMEM>>>(
        xhi, xlo, whi, wlo, bq, bk, bv, nullptr,
        qh, ql, kh, kl, vh, vl);

    flash_mma<<<dim3(Tc / 128, Hc, Bc), 256, FL_SMEM>>>(qh, ql, kh, kl, vh, vl, yhi, ylo);

    gemm_pk<0><<<dim3(Dc / 128, Mc / 128), 256, PK_SMEM>>>(
        yhi, ylo, whi + 3 * (size_t)DD, wlo + 3 * (size_t)DD, bo, nullptr, nullptr, out,
        nullptr, nullptr, nullptr, nullptr, nullptr, nullptr);
}

// round 9
// speedup vs baseline: 1.0654x; 1.0654x over previous
#include <cuda_runtime.h>
#include <cuda_bf16.h>
#include <math.h>
#include <stdint.h>

// Problem constants
#define Bc  2
#define Tc  2048
#define Dc  1024
#define Hc  16
#define HDc 64
#define Mc  (Bc * Tc)          // 4096
#define DD  (Dc * Dc)
#define ATTN_SCALE 0.125f

// Scratch (bf16 hi/lo everywhere)
static __device__ __align__(16) __nv_bfloat16 g_xhi[Mc * Dc], g_xlo[Mc * Dc];
static __device__ __align__(16) __nv_bfloat16 g_whi[4][DD], g_wlo[4][DD];
static __device__ __align__(16) __nv_bfloat16 g_qh[Mc * Dc], g_ql[Mc * Dc];
static __device__ __align__(16) __nv_bfloat16 g_kh[Mc * Dc], g_kl[Mc * Dc];
static __device__ __align__(16) __nv_bfloat16 g_vh[Mc * Dc], g_vl[Mc * Dc];
static __device__ __align__(16) __nv_bfloat16 g_yhi[Mc * Dc], g_ylo[Mc * Dc];

// ---------------------------------------------------------------------------
// PTX helpers — base-target-safe (mma.sync / ldmatrix / cp.async)
// ---------------------------------------------------------------------------
__device__ __forceinline__ uint32_t smem_u32(const void* p) {
    uint32_t a;
    asm("{ .reg .u64 t; cvta.to.shared.u64 t, %1; cvt.u32.u64 %0, t; }" : "=r"(a) : "l"(p));
    return a;
}
__device__ __forceinline__ void ldm_x4(uint32_t& r0, uint32_t& r1, uint32_t& r2,
                                       uint32_t& r3, uint32_t addr) {
    asm volatile("ldmatrix.sync.aligned.m8n8.x4.shared.b16 {%0,%1,%2,%3}, [%4];"
                 : "=r"(r0), "=r"(r1), "=r"(r2), "=r"(r3) : "r"(addr));
}
__device__ __forceinline__ void ldm_x4t(uint32_t& r0, uint32_t& r1, uint32_t& r2,
                                        uint32_t& r3, uint32_t addr) {
    asm volatile("ldmatrix.sync.aligned.m8n8.x4.trans.shared.b16 {%0,%1,%2,%3}, [%4];"
                 : "=r"(r0), "=r"(r1), "=r"(r2), "=r"(r3) : "r"(addr));
}
__device__ __forceinline__ void mma16816(float* d, const uint32_t* a, const uint32_t* b) {
    asm volatile("mma.sync.aligned.m16n8k16.row.col.f32.bf16.bf16.f32 "
                 "{%0,%1,%2,%3}, {%4,%5,%6,%7}, {%8,%9}, {%0,%1,%2,%3};"
                 : "+f"(d[0]), "+f"(d[1]), "+f"(d[2]), "+f"(d[3])
                 : "r"(a[0]), "r"(a[1]), "r"(a[2]), "r"(a[3]), "r"(b[0]), "r"(b[1]));
}
__device__ __forceinline__ void cp16(uint32_t dst, const void* src) {
    asm volatile("cp.async.cg.shared.global [%0], [%1], 16;" :: "r"(dst), "l"(src));
}
__device__ __forceinline__ void cp_commit() {
    asm volatile("cp.async.commit_group;" ::: "memory");
}
template <int N>
__device__ __forceinline__ void cp_wait() {
    asm volatile("cp.async.wait_group %0;" :: "n"(N) : "memory");
}
__device__ __forceinline__ uint32_t pack_hi2(float a, float b) {
    __nv_bfloat162 v = __floats2bfloat162_rn(a, b);
    return *(uint32_t*)&v;
}

// ---------------------------------------------------------------------------
// Fused fp32 -> bf16 hi/lo split: x + all 4 weights in one launch.
// ---------------------------------------------------------------------------
#define NX4 (Mc * Dc / 4)
#define NW4 (DD / 4)

__global__ void __launch_bounds__(256)
split_all(const float* __restrict__ x,
          const float* __restrict__ w0, const float* __restrict__ w1,
          const float* __restrict__ w2, const float* __restrict__ w3,
          __nv_bfloat16* __restrict__ xhi, __nv_bfloat16* __restrict__ xlo,
          __nv_bfloat16* __restrict__ whi, __nv_bfloat16* __restrict__ wlo)
{
    const size_t c = (size_t)blockIdx.x * 256 + threadIdx.x;
    const float* src;
    __nv_bfloat16 *ho, *lo_;
    if (c < NX4) {
        src = x + c * 4;
        ho = xhi + c * 4; lo_ = xlo + c * 4;
    } else {
        const size_t r = c - NX4;
        const int w = (int)(r >> 18);
        const size_t l = (r & (NW4 - 1)) * 4;
        const float* ws = (w == 0) ? w0 : (w == 1) ? w1 : (w == 2) ? w2 : w3;
        src = ws + l;
        ho = whi + (size_t)w * DD + l; lo_ = wlo + (size_t)w * DD + l;
    }
    const float4 v = *(const float4*)src;
    const __nv_bfloat16 h0 = __float2bfloat16(v.x);
    const __nv_bfloat16 h1 = __float2bfloat16(v.y);
    const __nv_bfloat16 h2 = __float2bfloat16(v.z);
    const __nv_bfloat16 h3 = __float2bfloat16(v.w);
    __nv_bfloat162 ha, hb, la, lb;
    ha.x = h0; ha.y = h1; hb.x = h2; hb.y = h3;
    la.x = __float2bfloat16(v.x - __bfloat162float(h0));
    la.y = __float2bfloat16(v.y - __bfloat162float(h1));
    lb.x = __float2bfloat16(v.z - __bfloat162float(h2));
    lb.y = __float2bfloat16(v.w - __bfloat162float(h3));
    ((__nv_bfloat162*)ho)[0] = ha; ((__nv_bfloat162*)ho)[1] = hb;
    ((__nv_bfloat162*)lo_)[0] = la; ((__nv_bfloat162*)lo_)[1] = lb;
}

// ---------------------------------------------------------------------------
// Fused QKV GEMM: per (m128, n64) block, compute Q, K, V reusing the same
// x hi/lo tiles. K-block 64, 2-stage cp.async, ONE barrier per k-block:
//   { cp_wait(own); __syncthreads(); issue(next); compute }
// ---------------------------------------------------------------------------
#define QKV_STAGE 81920
#define QKV_SMEM  (2 * QKV_STAGE)

__global__ void __launch_bounds__(256)
gemm_qkv(const __nv_bfloat16* __restrict__ Ahi, const __nv_bfloat16* __restrict__ Alo,
         const __nv_bfloat16* __restrict__ Wh, const __nv_bfloat16* __restrict__ Wl,
         const float* __restrict__ b0, const float* __restrict__ b1,
         const float* __restrict__ b2,
         __nv_bfloat16* __restrict__ qh, __nv_bfloat16* __restrict__ ql,
         __nv_bfloat16* __restrict__ kh, __nv_bfloat16* __restrict__ kl,
         __nv_bfloat16* __restrict__ vh, __nv_bfloat16* __restrict__ vl)
{
    extern __shared__ char smem[];
    const uint32_t sb = smem_u32(smem);
    const int tid = threadIdx.x;
    const int lane = tid & 31;
    const int wid = tid >> 5;
    const int m0 = blockIdx.y * 128;
    const int n0 = blockIdx.x * 64;
    const int wm = (wid & 1) * 64;
    const int wn = (wid >> 1) * 16;

    auto issue = [&](int kb, int bufo) {
#pragma unroll
        for (int it = 0; it < 8; it++) {
            const int idx = it * 256 + tid;
            const int tile = idx >> 10;
            const int r = (idx >> 3) & 127;
            const int ch = idx & 7;
            const uint32_t dst = sb + bufo + tile * 16384 + r * 128 +
                                 ((ch * 16) ^ ((r & 7) << 4));
            const __nv_bfloat16* src = tile ? Alo : Ahi;
            cp16(dst, src + (size_t)(m0 + r) * Dc + kb * 64 + ch * 8);
        }
#pragma unroll
        for (int it = 0; it < 12; it++) {
            const int idx = it * 256 + tid;
            const int wt = idx >> 9;
            const int r = (idx >> 3) & 63;
            const int ch = idx & 7;
            const uint32_t dst = sb + bufo + 32768 + wt * 8192 + r * 128 +
                                 ((ch * 16) ^ ((r & 7) << 4));
            const int w = wt >> 1;
            const __nv_bfloat16* src = (wt & 1) ? (Wl + (size_t)w * DD)
                                                : (Wh + (size_t)w * DD);
            cp16(dst, src + (size_t)(n0 + r) * Dc + kb * 64 + ch * 8);
        }
        cp_commit();
    };

    const int g = lane >> 3;
    const int lr = lane & 7;
    int aRow[4];
    uint32_t aSw[4];
#pragma unroll
    for (int mf = 0; mf < 4; mf++) {
        aRow[mf] = wm + mf * 16 + ((g & 1) ? 8 : 0) + lr;
        aSw[mf] = (uint32_t)((aRow[mf] & 7) << 4);
    }
    const uint32_t aKext = (g >= 2) ? 16u : 0u;
    const int bRow = wn + ((g >= 2) ? 8 : 0) + lr;
    const uint32_t bSw = (uint32_t)((bRow & 7) << 4);
    const uint32_t bKext = (g & 1) ? 16u : 0u;

    float acc[3][4][2][4];
#pragma unroll
    for (int w = 0; w < 3; w++)
#pragma unroll
        for (int mf = 0; mf < 4; mf++)
#pragma unroll
            for (int nf = 0; nf < 2; nf++)
#pragma unroll
                for (int q = 0; q < 4; q++) acc[w][mf][nf][q] = 0.0f;

    issue(0, 0);

    for (int kb = 0; kb < 16; kb++) {
        const int bufo = (kb & 1) * QKV_STAGE;
        cp_wait<0>();                 // own copies of group kb landed
        __syncthreads();              // everyone's landed; prior reads finished
        if (kb < 15) issue(kb + 1, QKV_STAGE - bufo);   // targets buf read at kb-1

        const uint32_t bA = sb + bufo;
#pragma unroll
        for (int ks = 0; ks < 4; ks++) {
            uint32_t ah[4][4], al[4][4];
#pragma unroll
            for (int mf = 0; mf < 4; mf++) {
                const uint32_t off = (uint32_t)(aRow[mf] * 128) +
                                     (((uint32_t)(ks * 32) + aKext) ^ aSw[mf]);
                ldm_x4(ah[mf][0], ah[mf][1], ah[mf][2], ah[mf][3], bA + off);
                ldm_x4(al[mf][0], al[mf][1], al[mf][2], al[mf][3], bA + 16384 + off);
            }
            const uint32_t boff = (uint32_t)(bRow * 128) +
                                  (((uint32_t)(ks * 32) + bKext) ^ bSw);
#pragma unroll
            for (int w = 0; w < 3; w++) {
                const uint32_t bWh = bA + 32768 + w * 16384;
                uint32_t bh[2][2], bl[2][2];
                ldm_x4(bh[0][0], bh[0][1], bh[1][0], bh[1][1], bWh + boff);
                ldm_x4(bl[0][0], bl[0][1], bl[1][0], bl[1][1], bWh + 8192 + boff);
#pragma unroll
                for (int mf = 0; mf < 4; mf++)
#pragma unroll
                    for (int nf = 0; nf < 2; nf++) {
                        mma16816(acc[w][mf][nf], ah[mf], bh[nf]);
                        mma16816(acc[w][mf][nf], ah[mf], bl[nf]);
                        mma16816(acc[w][mf][nf], al[mf], bh[nf]);
                    }
            }
        }
    }

    // Epilogue: head-layout bf16 hi/lo for each of Q, K, V
    const int tr = lane >> 2;
    const int tc2 = (lane & 3) * 2;
#pragma unroll
    for (int w = 0; w < 3; w++) {
        const float scl = (w == 0) ? ATTN_SCALE : 1.0f;
        const float* bias = (w == 0) ? b0 : (w == 1) ? b1 : b2;
        __nv_bfloat16* oh = (w == 0) ? qh : (w == 1) ? kh : vh;
        __nv_bfloat16* ol = (w == 0) ? ql : (w == 1) ? kl : vl;
#pragma unroll
        for (int mf = 0; mf < 4; mf++) {
#pragma unroll
            for (int nf = 0; nf < 2; nf++) {
                const int n = n0 + wn + nf * 8 + tc2;
                const float bb0 = bias[n], bb1 = bias[n + 1];
                const int mA = m0 + wm + mf * 16 + tr;
                const int mB = mA + 8;
                const float vA0 = (acc[w][mf][nf][0] + bb0) * scl;
                const float vA1 = (acc[w][mf][nf][1] + bb1) * scl;
                const float vB0 = (acc[w][mf][nf][2] + bb0) * scl;
                const float vB1 = (acc[w][mf][nf][3] + bb1) * scl;
                const int h = n >> 6, hd = n & 63;
                const int bA = mA >> 11, tA = mA & 2047;
                const int bB = mB >> 11, tB = mB & 2047;
                const size_t oA = ((size_t)(bA * Hc + h) * Tc + tA) * HDc + hd;
                const size_t oB = ((size_t)(bB * Hc + h) * Tc + tB) * HDc + hd;
                __nv_bfloat162 hA = __floats2bfloat162_rn(vA0, vA1);
                __nv_bfloat162 hB = __floats2bfloat162_rn(vB0, vB1);
                __nv_bfloat162 lA, lB;
                lA.x = __float2bfloat16(vA0 - __bfloat162float(hA.x));
                lA.y = __float2bfloat16(vA1 - __bfloat162float(hA.y));
                lB.x = __float2bfloat16(vB0 - __bfloat162float(hB.x));
                lB.y = __float2bfloat16(vB1 - __bfloat162float(hB.y));
                *(__nv_bfloat162*)(oh + oA) = hA;
                *(__nv_bfloat162*)(oh + oB) = hB;
                *(__nv_bfloat162*)(ol + oA) = lA;
                *(__nv_bfloat162*)(ol + oB) = lB;
            }
        }
    }
}

// ---------------------------------------------------------------------------
// Out-projection GEMM (fp32 out): 128x128 tile, K-block 64, 2-stage cp.async,
// one barrier per k-block (wait -> sync -> issue -> compute).
// ---------------------------------------------------------------------------
#define GEMM_SMEM (2 * 65536)

__global__ void __launch_bounds__(256)
gemm_out(const __nv_bfloat16* __restrict__ Ahi, const __nv_bfloat16* __restrict__ Alo,
         const __nv_bfloat16* __restrict__ Whi, const __nv_bfloat16* __restrict__ Wlo,
         const float* __restrict__ bias, float* __restrict__ C)
{
    extern __shared__ char smem[];
    const uint32_t sb = smem_u32(smem);
    const int tid = threadIdx.x;
    const int lane = tid & 31;
    const int wid = tid >> 5;
    const int m0 = blockIdx.y * 128;
    const int n0 = blockIdx.x * 128;
    const int wm = (wid & 1) * 64;
    const int wn = (wid >> 1) * 32;

    const __nv_bfloat16* src0 = Ahi + (size_t)m0 * Dc;
    const __nv_bfloat16* src1 = Alo + (size_t)m0 * Dc;
    const __nv_bfloat16* src2 = Whi + (size_t)n0 * Dc;
    const __nv_bfloat16* src3 = Wlo + (size_t)n0 * Dc;

    auto issue = [&](int kb, int bufo) {
        const __nv_bfloat16* srcs[4] = { src0, src1, src2, src3 };
#pragma unroll
        for (int tile = 0; tile < 4; tile++) {
#pragma unroll
            for (int it = 0; it < 4; it++) {
                const int idx = it * 256 + tid;
                const int r = idx >> 3;
                const int ch = idx & 7;
                const uint32_t dst = sb + bufo + tile * 16384 + r * 128 +
                                     ((ch * 16) ^ ((r & 7) << 4));
                cp16(dst, srcs[tile] + (size_t)r * Dc + kb * 64 + ch * 8);
            }
        }
        cp_commit();
    };

    const int g = lane >> 3;
    const int lr = lane & 7;
    int aRow[4];
    uint32_t aSw[4];
#pragma unroll
    for (int mf = 0; mf < 4; mf++) {
        aRow[mf] = wm + mf * 16 + ((g & 1) ? 8 : 0) + lr;
        aSw[mf] = (uint32_t)((aRow[mf] & 7) << 4);
    }
    const uint32_t aKext = (g >= 2) ? 16u : 0u;
    int bRow[2];
    uint32_t bSw[2];
#pragma unroll
    for (int p = 0; p < 2; p++) {
        bRow[p] = wn + p * 16 + ((g >= 2) ? 8 : 0) + lr;
        bSw[p] = (uint32_t)((bRow[p] & 7) << 4);
    }
    const uint32_t bKext = (g & 1) ? 16u : 0u;

    float acc[4][4][4];
#pragma unroll
    for (int mf = 0; mf < 4; mf++)
#pragma unroll
        for (int nf = 0; nf < 4; nf++)
#pragma unroll
            for (int q = 0; q < 4; q++) acc[mf][nf][q] = 0.0f;

    issue(0, 0);

    for (int kb = 0; kb < 16; kb++) {
        const int bufo = (kb & 1) * 65536;
        cp_wait<0>();
        __syncthreads();
        if (kb < 15) issue(kb + 1, 65536 - bufo);

        const uint32_t bAh = sb + bufo;
        const uint32_t bAl = bAh + 16384;
        const uint32_t bWh = bAh + 32768;
        const uint32_t bWl = bAh + 49152;

#pragma unroll
        for (int ks = 0; ks < 4; ks++) {
            const uint32_t ka = (uint32_t)(ks * 32) + aKext;
            const uint32_t kbyt = (uint32_t)(ks * 32) + bKext;
            uint32_t ah[4][4], al[4][4], bh[4][2], bl[4][2];
#pragma unroll
            for (int mf = 0; mf < 4; mf++) {
                const uint32_t off = (uint32_t)(aRow[mf] * 128) + (ka ^ aSw[mf]);
                ldm_x4(ah[mf][0], ah[mf][1], ah[mf][2], ah[mf][3], bAh + off);
                ldm_x4(al[mf][0], al[mf][1], al[mf][2], al[mf][3], bAl + off);
            }
#pragma unroll
            for (int p = 0; p < 2; p++) {
                const uint32_t off = (uint32_t)(bRow[p] * 128) + (kbyt ^ bSw[p]);
                ldm_x4(bh[2 * p][0], bh[2 * p][1], bh[2 * p + 1][0], bh[2 * p + 1][1],
                       bWh + off);
                ldm_x4(bl[2 * p][0], bl[2 * p][1], bl[2 * p + 1][0], bl[2 * p + 1][1],
                       bWl + off);
            }
#pragma unroll
            for (int mf = 0; mf < 4; mf++)
#pragma unroll
                for (int nf = 0; nf < 4; nf++) {
                    mma16816(acc[mf][nf], ah[mf], bh[nf]);
                    mma16816(acc[mf][nf], ah[mf], bl[nf]);
                    mma16816(acc[mf][nf], al[mf], bh[nf]);
                }
        }
    }

    const int tr = lane >> 2;
    const int tc2 = (lane & 3) * 2;
#pragma unroll
    for (int mf = 0; mf < 4; mf++) {
#pragma unroll
        for (int nf = 0; nf < 4; nf++) {
            const int n = n0 + wn + nf * 8 + tc2;
            const float b0 = bias[n], b1 = bias[n + 1];
            const int mA = m0 + wm + mf * 16 + tr;
            const int mB = mA + 8;
            float2 vA, vB;
            vA.x = acc[mf][nf][0] + b0; vA.y = acc[mf][nf][1] + b1;
            vB.x = acc[mf][nf][2] + b0; vB.y = acc[mf][nf][3] + b1;
            *(float2*)(C + (size_t)mA * Dc + n) = vA;
            *(float2*)(C + (size_t)mB * Dc + n) = vB;
        }
    }
}

// ---------------------------------------------------------------------------
// Tensor-core causal flash attention. BQ=128 (16 q-rows/warp), BKV=64.
// 3-stage cp.async KV pipeline, one barrier per tile (wait -> sync -> issue).
// ---------------------------------------------------------------------------
#define FL_SMEM (32768 + 3 * 32768)

__global__ void __launch_bounds__(256)
flash_mma(const __nv_bfloat16* __restrict__ Qh_, const __nv_bfloat16* __restrict__ Ql_,
          const __nv_bfloat16* __restrict__ Kh_, const __nv_bfloat16* __restrict__ Kl_,
          const __nv_bfloat16* __restrict__ Vh_, const __nv_bfloat16* __restrict__ Vl_,
          __nv_bfloat16* __restrict__ Yhi, __nv_bfloat16* __restrict__ Ylo)
{
    extern __shared__ char smem[];
    const uint32_t sb = smem_u32(smem);
    const int tid = threadIdx.x;
    const int lane = tid & 31;
    const int w = tid >> 5;
    const int qi = (int)(gridDim.x - 1) - (int)blockIdx.x;   // heavy tiles first
    const int q0 = qi * 128;
    const int h = blockIdx.y, b = blockIdx.z;
    const size_t base = (size_t)(b * Hc + h) * Tc * HDc;
    const __nv_bfloat16* Qh = Qh_ + base;
    const __nv_bfloat16* Ql = Ql_ + base;
    const __nv_bfloat16* Kh = Kh_ + base;
    const __nv_bfloat16* Kl = Kl_ + base;
    const __nv_bfloat16* Vh = Vh_ + base;
    const __nv_bfloat16* Vl = Vl_ + base;

    // Q tiles (Qh at 0, Ql at 16384) — own commit group
#pragma unroll
    for (int it = 0; it < 4; it++) {
        const int idx = it * 256 + tid;
        const int r = idx >> 3;
        const int ch = idx & 7;
        const uint32_t off = r * 128 + ((ch * 16) ^ ((r & 7) << 4));
        const size_t gi = (size_t)(q0 + r) * HDc + ch * 8;
        cp16(sb + off, Qh + gi);
        cp16(sb + 16384 + off, Ql + gi);
    }
    cp_commit();

    auto issueKV = [&](int t, int buf) {
        const int k0 = t * 64;
        const uint32_t so = sb + 32768 + buf * 32768;
#pragma unroll
        for (int it = 0; it < 2; it++) {
            const int idx = it * 256 + tid;
            const int r = idx >> 3;
            const int ch = idx & 7;
            const uint32_t off = r * 128 + ((ch * 16) ^ ((r & 7) << 4));
            const size_t gi = (size_t)(k0 + r) * HDc + ch * 8;
            cp16(so + off,         Kh + gi);
            cp16(so + 8192 + off,  Kl + gi);
            cp16(so + 16384 + off, Vh + gi);
            cp16(so + 24576 + off, Vl + gi);
        }
        cp_commit();
    };

    const int g = lane >> 3;
    const int lr = lane & 7;
    const int aRow = w * 16 + ((g & 1) ? 8 : 0) + lr;
    const uint32_t aSw = (uint32_t)((aRow & 7) << 4);
    const uint32_t aKext = (g >= 2) ? 16u : 0u;
    const int bRowBase = ((g >= 2) ? 8 : 0) + lr;
    const uint32_t bKext = (g & 1) ? 16u : 0u;
    const int vRow = lane & 15;
    const uint32_t vDext = (lane & 16) ? 16u : 0u;

    const int tr = lane >> 2;
    const int tc2 = (lane & 3) * 2;
    const int rowg0 = q0 + w * 16 + tr;
    const int rowg1 = rowg0 + 8;

    float mL[2] = { -INFINITY, -INFINITY };
    float lL[2] = { 0.0f, 0.0f };
    float o[8][4];
#pragma unroll
    for (int j = 0; j < 8; j++)
#pragma unroll
        for (int q = 0; q < 4; q++) o[j][q] = 0.0f;

    const int nt = q0 / 64 + 2;
    issueKV(0, 0);
    issueKV(1, 1);
    int nxt = 2;
    int nxtbuf = 2;
    int curbuf = 0;

    for (int t = 0; t < nt; t++) {
        const int k0 = t * 64;
        // groups issued so far: Q, KV_0..KV_{nxt-1}; need KV_t done.
        const int pend = nxt - 1 - t;          // allowed pending after wait (<=1)
        if (pend) cp_wait<1>(); else cp_wait<0>();
        __syncthreads();                        // visibility + prior reads done
        if (nxt < nt) {
            issueKV(nxt, nxtbuf);               // targets buf read at t-1 (safe)
            nxt++;
            nxtbuf = (nxtbuf + 1 == 3) ? 0 : nxtbuf + 1;
        }

        if (k0 <= q0 + w * 16 + 15) {
            const uint32_t so = sb + 32768 + curbuf * 32768;
            float s[8][4];
#pragma unroll
            for (int j = 0; j < 8; j++)
#pragma unroll
                for (int q = 0; q < 4; q++) s[j][q] = 0.0f;

            // S = Q K^T (3-term)
#pragma unroll
            for (int ks = 0; ks < 4; ks++) {
                const uint32_t ka = (uint32_t)(ks * 32) + aKext;
                uint32_t qh4[4], ql4[4];
                const uint32_t qoff = (uint32_t)(aRow * 128) + (ka ^ aSw);
                ldm_x4(qh4[0], qh4[1], qh4[2], qh4[3], sb + qoff);
                ldm_x4(ql4[0], ql4[1], ql4[2], ql4[3], sb + 16384 + qoff);
#pragma unroll
                for (int p = 0; p < 4; p++) {
                    const int row = p * 16 + bRowBase;
                    const uint32_t off = (uint32_t)(row * 128) +
                        (((uint32_t)(ks * 32) + bKext) ^ ((uint32_t)((row & 7) << 4)));
                    uint32_t kh2[2][2], kl2[2][2];
                    ldm_x4(kh2[0][0], kh2[0][1], kh2[1][0], kh2[1][1], so + off);
                    ldm_x4(kl2[0][0], kl2[0][1], kl2[1][0], kl2[1][1], so + 8192 + off);
#pragma unroll
                    for (int u = 0; u < 2; u++) {
                        mma16816(s[2 * p + u], qh4, kh2[u]);
                        mma16816(s[2 * p + u], qh4, kl2[u]);
                        mma16816(s[2 * p + u], ql4, kh2[u]);
                    }
                }
            }

            // Causal mask
            if (k0 + 63 > q0 + w * 16) {
#pragma unroll
                for (int j = 0; j < 8; j++) {
                    const int c = k0 + j * 8 + tc2;
                    if (c > rowg0)     s[j][0] = -INFINITY;
                    if (c + 1 > rowg0) s[j][1] = -INFINITY;
                    if (c > rowg1)     s[j][2] = -INFINITY;
                    if (c + 1 > rowg1) s[j][3] = -INFINITY;
                }
            }

            // Online softmax
#pragma unroll
            for (int half = 0; half < 2; half++) {
                const int i0 = half * 2;
                float mx = -INFINITY;
#pragma unroll
                for (int j = 0; j < 8; j++)
                    mx = fmaxf(mx, fmaxf(s[j][i0], s[j][i0 + 1]));
                mx = fmaxf(mx, __shfl_xor_sync(0xffffffffu, mx, 1));
                mx = fmaxf(mx, __shfl_xor_sync(0xffffffffu, mx, 2));
                const float mn = fmaxf(mL[half], mx);
                const float alpha = __expf(mL[half] - mn);
                float rs = 0.0f;
#pragma unroll
                for (int j = 0; j < 8; j++) {
                    const float p0 = __expf(s[j][i0] - mn);
                    const float p1 = __expf(s[j][i0 + 1] - mn);
                    s[j][i0] = p0; s[j][i0 + 1] = p1;
                    rs += p0 + p1;
                }
                rs += __shfl_xor_sync(0xffffffffu, rs, 1);
                rs += __shfl_xor_sync(0xffffffffu, rs, 2);
                lL[half] = lL[half] * alpha + rs;
                mL[half] = mn;
#pragma unroll
                for (int j = 0; j < 8; j++) {
                    o[j][i0] *= alpha;
                    o[j][i0 + 1] *= alpha;
                }
            }

            // O += P V (3-term)
#pragma unroll
            for (int ks = 0; ks < 4; ks++) {
                const int j0 = 2 * ks, j1 = j0 + 1;
                uint32_t pha[4], pla[4];
                {
                    const float a0 = s[j0][0], a1 = s[j0][1];
                    const float a2 = s[j0][2], a3 = s[j0][3];
                    const float c0 = s[j1][0], c1 = s[j1][1];
                    const float c2 = s[j1][2], c3 = s[j1][3];
                    pha[0] = pack_hi2(a0, a1); pha[1] = pack_hi2(a2, a3);
                    pha[2] = pack_hi2(c0, c1); pha[3] = pack_hi2(c2, c3);
                    const __nv_bfloat162* hp0 = (const __nv_bfloat162*)&pha[0];
                    const __nv_bfloat162* hp1 = (const __nv_bfloat162*)&pha[1];
                    const __nv_bfloat162* hp2 = (const __nv_bfloat162*)&pha[2];
                    const __nv_bfloat162* hp3 = (const __nv_bfloat162*)&pha[3];
                    pla[0] = pack_hi2(a0 - __bfloat162float(hp0->x), a1 - __bfloat162float(hp0->y));
                    pla[1] = pack_hi2(a2 - __bfloat162float(hp1->x), a3 - __bfloat162float(hp1->y));
                    pla[2] = pack_hi2(c0 - __bfloat162float(hp2->x), c1 - __bfloat162float(hp2->y));
                    pla[3] = pack_hi2(c2 - __bfloat162float(hp3->x), c3 - __bfloat162float(hp3->y));
                }
                const int vr = ks * 16 + vRow;
                const uint32_t vsw = (uint32_t)((vr & 7) << 4);
#pragma unroll
                for (int pp = 0; pp < 4; pp++) {
                    const uint32_t dbyte = (uint32_t)(pp * 32) + vDext;
                    const uint32_t off = (uint32_t)(vr * 128) + (dbyte ^ vsw);
                    uint32_t vh2[2][2], vl2[2][2];
                    ldm_x4t(vh2[0][0], vh2[0][1], vh2[1][0], vh2[1][1], so + 16384 + off);
                    ldm_x4t(vl2[0][0], vl2[0][1], vl2[1][0], vl2[1][1], so + 24576 + off);
#pragma unroll
                    for (int u = 0; u < 2; u++) {
                        mma16816(o[2 * pp + u], pha, vh2[u]);
                        mma16816(o[2 * pp + u], pha, vl2[u]);
                        mma16816(o[2 * pp + u], pla, vh2[u]);
                    }
                }
            }
        }
        curbuf = (curbuf + 1 == 3) ? 0 : curbuf + 1;
    }

    // Epilogue: y (B,T,D) bf16 hi/lo
    const float inv0 = 1.0f / lL[0];
    const float inv1 = 1.0f / lL[1];
#pragma unroll
    for (int j = 0; j < 8; j++) {
        const int col = h * HDc + j * 8 + tc2;
        const float y00 = o[j][0] * inv0, y01 = o[j][1] * inv0;
        const float y10 = o[j][2] * inv1, y11 = o[j][3] * inv1;
        const size_t o0 = ((size_t)(b * Tc + rowg0)) * Dc + col;
        const size_t o1 = ((size_t)(b * Tc + rowg1)) * Dc + col;
        __nv_bfloat162 h0 = __floats2bfloat162_rn(y00, y01);
        __nv_bfloat162 h1 = __floats2bfloat162_rn(y10, y11);
        __nv_bfloat162 l0, l1;
        l0.x = __float2bfloat16(y00 - __bfloat162float(h0.x));
        l0.y = __float2bfloat16(y01 - __bfloat162float(h0.y));
        l1.x = __float2bfloat16(y10 - __bfloat162float(h1.x));
        l1.y = __float2bfloat16(y11 - __bfloat162float(h1.y));
        *(__nv_bfloat162*)(Yhi + o0) = h0;
        *(__nv_bfloat162*)(Yhi + o1) = h1;
        *(__nv_bfloat162*)(Ylo + o0) = l0;
        *(__nv_bfloat162*)(Ylo + o1) = l1;
    }
}

// ---------------------------------------------------------------------------
// Launch
// ---------------------------------------------------------------------------
extern "C" void kernel_launch(void* const* d_in, const int* in_sizes, int n_in,
                              void* d_out, int out_size)
{
    const float* x  = (const float*)d_in[0];
    // d_in[1]: boolean causal mask (applied analytically)
    const float* Wq = (const float*)d_in[2];
    const float* bq = (const float*)d_in[3];
    const float* Wk = (const float*)d_in[4];
    const float* bk = (const float*)d_in[5];
    const float* Wv = (const float*)d_in[6];
    const float* bv = (const float*)d_in[7];
    const float* Wo = (const float*)d_in[8];
    const float* bo = (const float*)d_in[9];
    float* out = (float*)d_out;

    __nv_bfloat16 *xhi, *xlo, *whi, *wlo, *yhi, *ylo;
    __nv_bfloat16 *qh, *ql, *kh, *kl, *vh, *vl;
    cudaGetSymbolAddress((void**)&xhi, g_xhi);
    cudaGetSymbolAddress((void**)&xlo, g_xlo);
    cudaGetSymbolAddress((void**)&whi, g_whi);
    cudaGetSymbolAddress((void**)&wlo, g_wlo);
    cudaGetSymbolAddress((void**)&yhi, g_yhi);
    cudaGetSymbolAddress((void**)&ylo, g_ylo);
    cudaGetSymbolAddress((void**)&qh,  g_qh);
    cudaGetSymbolAddress((void**)&ql,  g_ql);
    cudaGetSymbolAddress((void**)&kh,  g_kh);
    cudaGetSymbolAddress((void**)&kl,  g_kl);
    cudaGetSymbolAddress((void**)&vh,  g_vh);
    cudaGetSymbolAddress((void**)&vl,  g_vl);

    cudaFuncSetAttribute(gemm_qkv, cudaFuncAttributeMaxDynamicSharedMemorySize, QKV_SMEM);
    cudaFuncSetAttribute(gemm_out, cudaFuncAttributeMaxDynamicSharedMemorySize, GEMM_SMEM);
    cudaFuncSetAttribute(flash_mma, cudaFuncAttributeMaxDynamicSharedMemorySize, FL_SMEM);

    // Fused splits: x + Wq,Wk,Wv,Wo -> bf16 hi/lo
    split_all<<<(NX4 + 4 * NW4) / 256, 256>>>(x, Wq, Wk, Wv, Wo, xhi, xlo, whi, wlo);

    // Fused QKV projection (x tiles reused across the 3 weight sets)
    gemm_qkv<<<dim3(Dc / 64, Mc / 128), 256, QKV_SMEM>>>(
        xhi, xlo, whi, wlo, bq, bk, bv, qh, ql, kh, kl, vh, vl);

    flash_mma<<<dim3(Tc / 128, Hc, Bc), 256, FL_SMEM>>>(qh, ql, kh, kl, vh, vl, yhi, ylo);

    gemm_out<<<dim3(Dc / 128, Mc / 128), 256, GEMM_SMEM>>>(
        yhi, ylo, whi + 3 * (size_t)DD, wlo + 3 * (size_t)DD, bo, out);
}

// round 10
// speedup vs baseline: 1.1190x; 1.0503x over previous
#include <cuda_runtime.h>
#include <cuda_bf16.h>
#include <math.h>
#include <stdint.h>

// Problem constants
#define Bc  2
#define Tc  2048
#define Dc  1024
#define Hc  16
#define HDc 64
#define Mc  (Bc * Tc)          // 4096
#define DD  (Dc * Dc)
#define ATTN_SCALE 0.125f

// Scratch (bf16 hi/lo everywhere)
static __device__ __align__(16) __nv_bfloat16 g_xhi[Mc * Dc], g_xlo[Mc * Dc];
static __device__ __align__(16) __nv_bfloat16 g_whi[4][DD], g_wlo[4][DD];
static __device__ __align__(16) __nv_bfloat16 g_qh[Mc * Dc], g_ql[Mc * Dc];
static __device__ __align__(16) __nv_bfloat16 g_kh[Mc * Dc], g_kl[Mc * Dc];
static __device__ __align__(16) __nv_bfloat16 g_vh[Mc * Dc], g_vl[Mc * Dc];
static __device__ __align__(16) __nv_bfloat16 g_yhi[Mc * Dc], g_ylo[Mc * Dc];

// ---------------------------------------------------------------------------
// PTX helpers — base-target-safe (mma.sync / ldmatrix / cp.async)
// ---------------------------------------------------------------------------
__device__ __forceinline__ uint32_t smem_u32(const void* p) {
    uint32_t a;
    asm("{ .reg .u64 t; cvta.to.shared.u64 t, %1; cvt.u32.u64 %0, t; }" : "=r"(a) : "l"(p));
    return a;
}
__device__ __forceinline__ void ldm_x4(uint32_t& r0, uint32_t& r1, uint32_t& r2,
                                       uint32_t& r3, uint32_t addr) {
    asm volatile("ldmatrix.sync.aligned.m8n8.x4.shared.b16 {%0,%1,%2,%3}, [%4];"
                 : "=r"(r0), "=r"(r1), "=r"(r2), "=r"(r3) : "r"(addr));
}
__device__ __forceinline__ void ldm_x4t(uint32_t& r0, uint32_t& r1, uint32_t& r2,
                                        uint32_t& r3, uint32_t addr) {
    asm volatile("ldmatrix.sync.aligned.m8n8.x4.trans.shared.b16 {%0,%1,%2,%3}, [%4];"
                 : "=r"(r0), "=r"(r1), "=r"(r2), "=r"(r3) : "r"(addr));
}
__device__ __forceinline__ void mma16816(float* d, const uint32_t* a, const uint32_t* b) {
    asm volatile("mma.sync.aligned.m16n8k16.row.col.f32.bf16.bf16.f32 "
                 "{%0,%1,%2,%3}, {%4,%5,%6,%7}, {%8,%9}, {%0,%1,%2,%3};"
                 : "+f"(d[0]), "+f"(d[1]), "+f"(d[2]), "+f"(d[3])
                 : "r"(a[0]), "r"(a[1]), "r"(a[2]), "r"(a[3]), "r"(b[0]), "r"(b[1]));
}
__device__ __forceinline__ void cp16(uint32_t dst, const void* src) {
    asm volatile("cp.async.cg.shared.global [%0], [%1], 16;" :: "r"(dst), "l"(src));
}
__device__ __forceinline__ void cp_commit() {
    asm volatile("cp.async.commit_group;" ::: "memory");
}
template <int N>
__device__ __forceinline__ void cp_wait() {
    asm volatile("cp.async.wait_group %0;" :: "n"(N) : "memory");
}
__device__ __forceinline__ uint32_t pack_hi2(float a, float b) {
    __nv_bfloat162 v = __floats2bfloat162_rn(a, b);
    return *(uint32_t*)&v;
}

// ---------------------------------------------------------------------------
// Fused fp32 -> bf16 hi/lo split: x + all 4 weights in one launch.
// ---------------------------------------------------------------------------
#define NX4 (Mc * Dc / 4)
#define NW4 (DD / 4)

__global__ void __launch_bounds__(256)
split_all(const float* __restrict__ x,
          const float* __restrict__ w0, const float* __restrict__ w1,
          const float* __restrict__ w2, const float* __restrict__ w3,
          __nv_bfloat16* __restrict__ xhi, __nv_bfloat16* __restrict__ xlo,
          __nv_bfloat16* __restrict__ whi, __nv_bfloat16* __restrict__ wlo)
{
    const size_t c = (size_t)blockIdx.x * 256 + threadIdx.x;
    const float* src;
    __nv_bfloat16 *ho, *lo_;
    if (c < NX4) {
        src = x + c * 4;
        ho = xhi + c * 4; lo_ = xlo + c * 4;
    } else {
        const size_t r = c - NX4;
        const int w = (int)(r >> 18);
        const size_t l = (r & (NW4 - 1)) * 4;
        const float* ws = (w == 0) ? w0 : (w == 1) ? w1 : (w == 2) ? w2 : w3;
        src = ws + l;
        ho = whi + (size_t)w * DD + l; lo_ = wlo + (size_t)w * DD + l;
    }
    const float4 v = *(const float4*)src;
    const __nv_bfloat16 h0 = __float2bfloat16(v.x);
    const __nv_bfloat16 h1 = __float2bfloat16(v.y);
    const __nv_bfloat16 h2 = __float2bfloat16(v.z);
    const __nv_bfloat16 h3 = __float2bfloat16(v.w);
    __nv_bfloat162 ha, hb, la, lb;
    ha.x = h0; ha.y = h1; hb.x = h2; hb.y = h3;
    la.x = __float2bfloat16(v.x - __bfloat162float(h0));
    la.y = __float2bfloat16(v.y - __bfloat162float(h1));
    lb.x = __float2bfloat16(v.z - __bfloat162float(h2));
    lb.y = __float2bfloat16(v.w - __bfloat162float(h3));
    ((__nv_bfloat162*)ho)[0] = ha; ((__nv_bfloat162*)ho)[1] = hb;
    ((__nv_bfloat162*)lo_)[0] = la; ((__nv_bfloat162*)lo_)[1] = lb;
}

// ---------------------------------------------------------------------------
// GEMM, occupancy-tuned: CTA tile 128x64, K-block 64, 2-stage cp.async,
// stage = A(32K) + W(16K) = 48 KB -> 96 KB total -> 2 CTAs/SM (regs <= 128).
// Warp tile 64x16 (8 warps = 2m x 4n). One barrier per k-block.
// MODE 0: fp32 out C[m*Dc+n] (n0 in [0,1024)).
// MODE 1: flat N=3072 QKV -> head-layout bf16 hi/lo (+scale on Q).
// ---------------------------------------------------------------------------
#define RC_STAGE 49152
#define RC_SMEM  (2 * RC_STAGE)

template <int MODE>
__global__ void __launch_bounds__(256, 2)
gemm_rc(const __nv_bfloat16* __restrict__ Ahi, const __nv_bfloat16* __restrict__ Alo,
        const __nv_bfloat16* __restrict__ Wh, const __nv_bfloat16* __restrict__ Wl,
        const float* __restrict__ b0, const float* __restrict__ b1,
        const float* __restrict__ b2, float* __restrict__ C,
        __nv_bfloat16* __restrict__ qh, __nv_bfloat16* __restrict__ ql,
        __nv_bfloat16* __restrict__ kh, __nv_bfloat16* __restrict__ kl,
        __nv_bfloat16* __restrict__ vh, __nv_bfloat16* __restrict__ vl)
{
    extern __shared__ char smem[];
    const uint32_t sb = smem_u32(smem);
    const int tid = threadIdx.x;
    const int lane = tid & 31;
    const int wid = tid >> 5;
    const int m0 = blockIdx.y * 128;
    const int n0 = blockIdx.x * 64;      // flat n (MODE1: 0..3071)
    const int wm = (wid & 1) * 64;
    const int wn = (wid >> 1) * 16;

    auto issue = [&](int kb, int bufo) {
        // A: hi tile then lo tile, 128 rows x 8 chunks each (8 iters total)
#pragma unroll
        for (int it = 0; it < 8; it++) {
            const int idx = it * 256 + tid;      // 0..2047
            const int tile = idx >> 10;          // 0=hi, 1=lo
            const int r = (idx >> 3) & 127;
            const int ch = idx & 7;
            const uint32_t dst = sb + bufo + tile * 16384 + r * 128 +
                                 ((ch * 16) ^ ((r & 7) << 4));
            const __nv_bfloat16* src = tile ? Alo : Ahi;
            cp16(dst, src + (size_t)(m0 + r) * Dc + kb * 64 + ch * 8);
        }
        // W: hi then lo, 64 rows x 8 chunks each (4 iters total)
#pragma unroll
        for (int it = 0; it < 4; it++) {
            const int idx = it * 256 + tid;      // 0..1023
            const int wt = idx >> 9;             // 0=hi, 1=lo
            const int r = (idx >> 3) & 63;
            const int ch = idx & 7;
            const uint32_t dst = sb + bufo + 32768 + wt * 8192 + r * 128 +
                                 ((ch * 16) ^ ((r & 7) << 4));
            const __nv_bfloat16* src = wt ? Wl : Wh;
            cp16(dst, src + (size_t)(n0 + r) * Dc + kb * 64 + ch * 8);
        }
        cp_commit();
    };

    const int g = lane >> 3;
    const int lr = lane & 7;
    int aRow[4];
    uint32_t aSw[4];
#pragma unroll
    for (int mf = 0; mf < 4; mf++) {
        aRow[mf] = wm + mf * 16 + ((g & 1) ? 8 : 0) + lr;
        aSw[mf] = (uint32_t)((aRow[mf] & 7) << 4);
    }
    const uint32_t aKext = (g >= 2) ? 16u : 0u;
    const int bRow = wn + ((g >= 2) ? 8 : 0) + lr;       // < 64
    const uint32_t bSw = (uint32_t)((bRow & 7) << 4);
    const uint32_t bKext = (g & 1) ? 16u : 0u;

    float acc[4][2][4];
#pragma unroll
    for (int mf = 0; mf < 4; mf++)
#pragma unroll
        for (int nf = 0; nf < 2; nf++)
#pragma unroll
            for (int q = 0; q < 4; q++) acc[mf][nf][q] = 0.0f;

    issue(0, 0);

    for (int kb = 0; kb < 16; kb++) {
        const int bufo = (kb & 1) * RC_STAGE;
        cp_wait<0>();                 // own copies of group kb landed
        __syncthreads();              // everyone's landed; prior reads finished
        if (kb < 15) issue(kb + 1, RC_STAGE - bufo);

        const uint32_t bA = sb + bufo;
        const uint32_t bW = bA + 32768;
#pragma unroll
        for (int ks = 0; ks < 4; ks++) {
            uint32_t ah[4][4], al[4][4];
#pragma unroll
            for (int mf = 0; mf < 4; mf++) {
                const uint32_t off = (uint32_t)(aRow[mf] * 128) +
                                     (((uint32_t)(ks * 32) + aKext) ^ aSw[mf]);
                ldm_x4(ah[mf][0], ah[mf][1], ah[mf][2], ah[mf][3], bA + off);
                ldm_x4(al[mf][0], al[mf][1], al[mf][2], al[mf][3], bA + 16384 + off);
            }
            const uint32_t boff = (uint32_t)(bRow * 128) +
                                  (((uint32_t)(ks * 32) + bKext) ^ bSw);
            uint32_t bh[2][2], bl[2][2];
            ldm_x4(bh[0][0], bh[0][1], bh[1][0], bh[1][1], bW + boff);
            ldm_x4(bl[0][0], bl[0][1], bl[1][0], bl[1][1], bW + 8192 + boff);
#pragma unroll
            for (int mf = 0; mf < 4; mf++)
#pragma unroll
                for (int nf = 0; nf < 2; nf++) {
                    mma16816(acc[mf][nf], ah[mf], bh[nf]);
                    mma16816(acc[mf][nf], ah[mf], bl[nf]);
                    mma16816(acc[mf][nf], al[mf], bh[nf]);
                }
        }
    }

    const int tr = lane >> 2;
    const int tc2 = (lane & 3) * 2;

    if (MODE == 0) {
#pragma unroll
        for (int mf = 0; mf < 4; mf++)
#pragma unroll
            for (int nf = 0; nf < 2; nf++) {
                const int n = n0 + wn + nf * 8 + tc2;
                const float bb0 = b0[n], bb1 = b0[n + 1];
                const int mA = m0 + wm + mf * 16 + tr;
                const int mB = mA + 8;
                float2 vA, vB;
                vA.x = acc[mf][nf][0] + bb0; vA.y = acc[mf][nf][1] + bb1;
                vB.x = acc[mf][nf][2] + bb0; vB.y = acc[mf][nf][3] + bb1;
                *(float2*)(C + (size_t)mA * Dc + n) = vA;
                *(float2*)(C + (size_t)mB * Dc + n) = vB;
            }
    } else {
        const int w = n0 >> 10;              // which weight (whole CTA)
        const int nl0 = n0 & 1023;
        const float scl = (w == 0) ? ATTN_SCALE : 1.0f;
        const float* bias = (w == 0) ? b0 : (w == 1) ? b1 : b2;
        __nv_bfloat16* oh = (w == 0) ? qh : (w == 1) ? kh : vh;
        __nv_bfloat16* ol = (w == 0) ? ql : (w == 1) ? kl : vl;
#pragma unroll
        for (int mf = 0; mf < 4; mf++)
#pragma unroll
            for (int nf = 0; nf < 2; nf++) {
                const int n = nl0 + wn + nf * 8 + tc2;
                const float bb0 = bias[n], bb1 = bias[n + 1];
                const int mA = m0 + wm + mf * 16 + tr;
                const int mB = mA + 8;
                const float vA0 = (acc[mf][nf][0] + bb0) * scl;
                const float vA1 = (acc[mf][nf][1] + bb1) * scl;
                const float vB0 = (acc[mf][nf][2] + bb0) * scl;
                const float vB1 = (acc[mf][nf][3] + bb1) * scl;
                const int hh = n >> 6, hd = n & 63;
                const int bA = mA >> 11, tA = mA & 2047;
                const int bB = mB >> 11, tB = mB & 2047;
                const size_t oA = ((size_t)(bA * Hc + hh) * Tc + tA) * HDc + hd;
                const size_t oB = ((size_t)(bB * Hc + hh) * Tc + tB) * HDc + hd;
                __nv_bfloat162 hA = __floats2bfloat162_rn(vA0, vA1);
                __nv_bfloat162 hB = __floats2bfloat162_rn(vB0, vB1);
                __nv_bfloat162 lA, lB;
                lA.x = __float2bfloat16(vA0 - __bfloat162float(hA.x));
                lA.y = __float2bfloat16(vA1 - __bfloat162float(hA.y));
                lB.x = __float2bfloat16(vB0 - __bfloat162float(hB.x));
                lB.y = __float2bfloat16(vB1 - __bfloat162float(hB.y));
                *(__nv_bfloat162*)(oh + oA) = hA;
                *(__nv_bfloat162*)(oh + oB) = hB;
                *(__nv_bfloat162*)(ol + oA) = lA;
                *(__nv_bfloat162*)(ol + oB) = lB;
            }
    }
}

// ---------------------------------------------------------------------------
// Tensor-core causal flash attention (R9 known-good). BQ=128, BKV=64.
// 3-stage cp.async KV pipeline, one barrier per tile.
// ---------------------------------------------------------------------------
#define FL_SMEM (32768 + 3 * 32768)

__global__ void __launch_bounds__(256)
flash_mma(const __nv_bfloat16* __restrict__ Qh_, const __nv_bfloat16* __restrict__ Ql_,
          const __nv_bfloat16* __restrict__ Kh_, const __nv_bfloat16* __restrict__ Kl_,
          const __nv_bfloat16* __restrict__ Vh_, const __nv_bfloat16* __restrict__ Vl_,
          __nv_bfloat16* __restrict__ Yhi, __nv_bfloat16* __restrict__ Ylo)
{
    extern __shared__ char smem[];
    const uint32_t sb = smem_u32(smem);
    const int tid = threadIdx.x;
    const int lane = tid & 31;
    const int w = tid >> 5;
    const int qi = (int)(gridDim.x - 1) - (int)blockIdx.x;   // heavy tiles first
    const int q0 = qi * 128;
    const int h = blockIdx.y, b = blockIdx.z;
    const size_t base = (size_t)(b * Hc + h) * Tc * HDc;
    const __nv_bfloat16* Qh = Qh_ + base;
    const __nv_bfloat16* Ql = Ql_ + base;
    const __nv_bfloat16* Kh = Kh_ + base;
    const __nv_bfloat16* Kl = Kl_ + base;
    const __nv_bfloat16* Vh = Vh_ + base;
    const __nv_bfloat16* Vl = Vl_ + base;

    // Q tiles (Qh at 0, Ql at 16384) — own commit group
#pragma unroll
    for (int it = 0; it < 4; it++) {
        const int idx = it * 256 + tid;
        const int r = idx >> 3;
        const int ch = idx & 7;
        const uint32_t off = r * 128 + ((ch * 16) ^ ((r & 7) << 4));
        const size_t gi = (size_t)(q0 + r) * HDc + ch * 8;
        cp16(sb + off, Qh + gi);
        cp16(sb + 16384 + off, Ql + gi);
    }
    cp_commit();

    auto issueKV = [&](int t, int buf) {
        const int k0 = t * 64;
        const uint32_t so = sb + 32768 + buf * 32768;
#pragma unroll
        for (int it = 0; it < 2; it++) {
            const int idx = it * 256 + tid;
            const int r = idx >> 3;
            const int ch = idx & 7;
            const uint32_t off = r * 128 + ((ch * 16) ^ ((r & 7) << 4));
            const size_t gi = (size_t)(k0 + r) * HDc + ch * 8;
            cp16(so + off,         Kh + gi);
            cp16(so + 8192 + off,  Kl + gi);
            cp16(so + 16384 + off, Vh + gi);
            cp16(so + 24576 + off, Vl + gi);
        }
        cp_commit();
    };

    const int g = lane >> 3;
    const int lr = lane & 7;
    const int aRow = w * 16 + ((g & 1) ? 8 : 0) + lr;
    const uint32_t aSw = (uint32_t)((aRow & 7) << 4);
    const uint32_t aKext = (g >= 2) ? 16u : 0u;
    const int bRowBase = ((g >= 2) ? 8 : 0) + lr;
    const uint32_t bKext = (g & 1) ? 16u : 0u;
    const int vRow = lane & 15;
    const uint32_t vDext = (lane & 16) ? 16u : 0u;

    const int tr = lane >> 2;
    const int tc2 = (lane & 3) * 2;
    const int rowg0 = q0 + w * 16 + tr;
    const int rowg1 = rowg0 + 8;

    float mL[2] = { -INFINITY, -INFINITY };
    float lL[2] = { 0.0f, 0.0f };
    float o[8][4];
#pragma unroll
    for (int j = 0; j < 8; j++)
#pragma unroll
        for (int q = 0; q < 4; q++) o[j][q] = 0.0f;

    const int nt = q0 / 64 + 2;
    issueKV(0, 0);
    issueKV(1, 1);
    int nxt = 2;
    int nxtbuf = 2;
    int curbuf = 0;

    for (int t = 0; t < nt; t++) {
        const int k0 = t * 64;
        const int pend = nxt - 1 - t;
        if (pend) cp_wait<1>(); else cp_wait<0>();
        __syncthreads();
        if (nxt < nt) {
            issueKV(nxt, nxtbuf);
            nxt++;
            nxtbuf = (nxtbuf + 1 == 3) ? 0 : nxtbuf + 1;
        }

        if (k0 <= q0 + w * 16 + 15) {
            const uint32_t so = sb + 32768 + curbuf * 32768;
            float s[8][4];
#pragma unroll
            for (int j = 0; j < 8; j++)
#pragma unroll
                for (int q = 0; q < 4; q++) s[j][q] = 0.0f;

            // S = Q K^T (3-term)
#pragma unroll
            for (int ks = 0; ks < 4; ks++) {
                const uint32_t ka = (uint32_t)(ks * 32) + aKext;
                uint32_t qh4[4], ql4[4];
                const uint32_t qoff = (uint32_t)(aRow * 128) + (ka ^ aSw);
                ldm_x4(qh4[0], qh4[1], qh4[2], qh4[3], sb + qoff);
                ldm_x4(ql4[0], ql4[1], ql4[2], ql4[3], sb + 16384 + qoff);
#pragma unroll
                for (int p = 0; p < 4; p++) {
                    const int row = p * 16 + bRowBase;
                    const uint32_t off = (uint32_t)(row * 128) +
                        (((uint32_t)(ks * 32) + bKext) ^ ((uint32_t)((row & 7) << 4)));
                    uint32_t kh2[2][2], kl2[2][2];
                    ldm_x4(kh2[0][0], kh2[0][1], kh2[1][0], kh2[1][1], so + off);
                    ldm_x4(kl2[0][0], kl2[0][1], kl2[1][0], kl2[1][1], so + 8192 + off);
#pragma unroll
                    for (int u = 0; u < 2; u++) {
                        mma16816(s[2 * p + u], qh4, kh2[u]);
                        mma16816(s[2 * p + u], qh4, kl2[u]);
                        mma16816(s[2 * p + u], ql4, kh2[u]);
                    }
                }
            }

            // Causal mask
            if (k0 + 63 > q0 + w * 16) {
#pragma unroll
                for (int j = 0; j < 8; j++) {
                    const int c = k0 + j * 8 + tc2;
                    if (c > rowg0)     s[j][0] = -INFINITY;
                    if (c + 1 > rowg0) s[j][1] = -INFINITY;
                    if (c > rowg1)     s[j][2] = -INFINITY;
                    if (c + 1 > rowg1) s[j][3] = -INFINITY;
                }
            }

            // Online softmax
#pragma unroll
            for (int half = 0; half < 2; half++) {
                const int i0 = half * 2;
                float mx = -INFINITY;
#pragma unroll
                for (int j = 0; j < 8; j++)
                    mx = fmaxf(mx, fmaxf(s[j][i0], s[j][i0 + 1]));
                mx = fmaxf(mx, __shfl_xor_sync(0xffffffffu, mx, 1));
                mx = fmaxf(mx, __shfl_xor_sync(0xffffffffu, mx, 2));
                const float mn = fmaxf(mL[half], mx);
                const float alpha = __expf(mL[half] - mn);
                float rs = 0.0f;
#pragma unroll
                for (int j = 0; j < 8; j++) {
                    const float p0 = __expf(s[j][i0] - mn);
                    const float p1 = __expf(s[j][i0 + 1] - mn);
                    s[j][i0] = p0; s[j][i0 + 1] = p1;
                    rs += p0 + p1;
                }
                rs += __shfl_xor_sync(0xffffffffu, rs, 1);
                rs += __shfl_xor_sync(0xffffffffu, rs, 2);
                lL[half] = lL[half] * alpha + rs;
                mL[half] = mn;
#pragma unroll
                for (int j = 0; j < 8; j++) {
                    o[j][i0] *= alpha;
                    o[j][i0 + 1] *= alpha;
                }
            }

            // O += P V (3-term)
#pragma unroll
            for (int ks = 0; ks < 4; ks++) {
                const int j0 = 2 * ks, j1 = j0 + 1;
                uint32_t pha[4], pla[4];
                {
                    const float a0 = s[j0][0], a1 = s[j0][1];
                    const float a2 = s[j0][2], a3 = s[j0][3];
                    const float c0 = s[j1][0], c1 = s[j1][1];
                    const float c2 = s[j1][2], c3 = s[j1][3];
                    pha[0] = pack_hi2(a0, a1); pha[1] = pack_hi2(a2, a3);
                    pha[2] = pack_hi2(c0, c1); pha[3] = pack_hi2(c2, c3);
                    const __nv_bfloat162* hp0 = (const __nv_bfloat162*)&pha[0];
                    const __nv_bfloat162* hp1 = (const __nv_bfloat162*)&pha[1];
                    const __nv_bfloat162* hp2 = (const __nv_bfloat162*)&pha[2];
                    const __nv_bfloat162* hp3 = (const __nv_bfloat162*)&pha[3];
                    pla[0] = pack_hi2(a0 - __bfloat162float(hp0->x), a1 - __bfloat162float(hp0->y));
                    pla[1] = pack_hi2(a2 - __bfloat162float(hp1->x), a3 - __bfloat162float(hp1->y));
                    pla[2] = pack_hi2(c0 - __bfloat162float(hp2->x), c1 - __bfloat162float(hp2->y));
                    pla[3] = pack_hi2(c2 - __bfloat162float(hp3->x), c3 - __bfloat162float(hp3->y));
                }
                const int vr = ks * 16 + vRow;
                const uint32_t vsw = (uint32_t)((vr & 7) << 4);
#pragma unroll
                for (int pp = 0; pp < 4; pp++) {
                    const uint32_t dbyte = (uint32_t)(pp * 32) + vDext;
                    const uint32_t off = (uint32_t)(vr * 128) + (dbyte ^ vsw);
                    uint32_t vh2[2][2], vl2[2][2];
                    ldm_x4t(vh2[0][0], vh2[0][1], vh2[1][0], vh2[1][1], so + 16384 + off);
                    ldm_x4t(vl2[0][0], vl2[0][1], vl2[1][0], vl2[1][1], so + 24576 + off);
#pragma unroll
                    for (int u = 0; u < 2; u++) {
                        mma16816(o[2 * pp + u], pha, vh2[u]);
                        mma16816(o[2 * pp + u], pha, vl2[u]);
                        mma16816(o[2 * pp + u], pla, vh2[u]);
                    }
                }
            }
        }
        curbuf = (curbuf + 1 == 3) ? 0 : curbuf + 1;
    }

    // Epilogue: y (B,T,D) bf16 hi/lo
    const float inv0 = 1.0f / lL[0];
    const float inv1 = 1.0f / lL[1];
#pragma unroll
    for (int j = 0; j < 8; j++) {
        const int col = h * HDc + j * 8 + tc2;
        const float y00 = o[j][0] * inv0, y01 = o[j][1] * inv0;
        const float y10 = o[j][2] * inv1, y11 = o[j][3] * inv1;
        const size_t o0 = ((size_t)(b * Tc + rowg0)) * Dc + col;
        const size_t o1 = ((size_t)(b * Tc + rowg1)) * Dc + col;
        __nv_bfloat162 h0 = __floats2bfloat162_rn(y00, y01);
        __nv_bfloat162 h1 = __floats2bfloat162_rn(y10, y11);
        __nv_bfloat162 l0, l1;
        l0.x = __float2bfloat16(y00 - __bfloat162float(h0.x));
        l0.y = __float2bfloat16(y01 - __bfloat162float(h0.y));
        l1.x = __float2bfloat16(y10 - __bfloat162float(h1.x));
        l1.y = __float2bfloat16(y11 - __bfloat162float(h1.y));
        *(__nv_bfloat162*)(Yhi + o0) = h0;
        *(__nv_bfloat162*)(Yhi + o1) = h1;
        *(__nv_bfloat162*)(Ylo + o0) = l0;
        *(__nv_bfloat162*)(Ylo + o1) = l1;
    }
}

// ---------------------------------------------------------------------------
// Launch
// ---------------------------------------------------------------------------
extern "C" void kernel_launch(void* const* d_in, const int* in_sizes, int n_in,
                              void* d_out, int out_size)
{
    const float* x  = (const float*)d_in[0];
    // d_in[1]: boolean causal mask (applied analytically)
    const float* Wq = (const float*)d_in[2];
    const float* bq = (const float*)d_in[3];
    const float* Wk = (const float*)d_in[4];
    const float* bk = (const float*)d_in[5];
    const float* Wv = (const float*)d_in[6];
    const float* bv = (const float*)d_in[7];
    const float* Wo = (const float*)d_in[8];
    const float* bo = (const float*)d_in[9];
    float* out = (float*)d_out;

    __nv_bfloat16 *xhi, *xlo, *whi, *wlo, *yhi, *ylo;
    __nv_bfloat16 *qh, *ql, *kh, *kl, *vh, *vl;
    cudaGetSymbolAddress((void**)&xhi, g_xhi);
    cudaGetSymbolAddress((void**)&xlo, g_xlo);
    cudaGetSymbolAddress((void**)&whi, g_whi);
    cudaGetSymbolAddress((void**)&wlo, g_wlo);
    cudaGetSymbolAddress((void**)&yhi, g_yhi);
    cudaGetSymbolAddress((void**)&ylo, g_ylo);
    cudaGetSymbolAddress((void**)&qh,  g_qh);
    cudaGetSymbolAddress((void**)&ql,  g_ql);
    cudaGetSymbolAddress((void**)&kh,  g_kh);
    cudaGetSymbolAddress((void**)&kl,  g_kl);
    cudaGetSymbolAddress((void**)&vh,  g_vh);
    cudaGetSymbolAddress((void**)&vl,  g_vl);

    cudaFuncSetAttribute(gemm_rc<0>, cudaFuncAttributeMaxDynamicSharedMemorySize, RC_SMEM);
    cudaFuncSetAttribute(gemm_rc<1>, cudaFuncAttributeMaxDynamicSharedMemorySize, RC_SMEM);
    cudaFuncSetAttribute(flash_mma, cudaFuncAttributeMaxDynamicSharedMemorySize, FL_SMEM);

    // Fused splits: x + Wq,Wk,Wv,Wo -> bf16 hi/lo
    split_all<<<(NX4 + 4 * NW4) / 256, 256>>>(x, Wq, Wk, Wv, Wo, xhi, xlo, whi, wlo);

    // QKV as one flat N=3072 GEMM over concatenated weights
    gemm_rc<1><<<dim3(3 * Dc / 64, Mc / 128), 256, RC_SMEM>>>(
        xhi, xlo, whi, wlo, bq, bk, bv, nullptr,
        qh, ql, kh, kl, vh, vl);

    flash_mma<<<dim3(Tc / 128, Hc, Bc), 256, FL_SMEM>>>(qh, ql, kh, kl, vh, vl, yhi, ylo);

    gemm_rc<0><<<dim3(Dc / 64, Mc / 128), 256, RC_SMEM>>>(
        yhi, ylo, whi + 3 * (size_t)DD, wlo + 3 * (size_t)DD, bo, nullptr, nullptr, out,
        nullptr, nullptr, nullptr, nullptr, nullptr, nullptr);
}